// round 6
// baseline (speedup 1.0000x reference)
#include <cuda_runtime.h>
#include <cuda_bf16.h>
#include <math.h>
#include <stdint.h>

#define Rr   10000
#define E    256
#define Bb   1024
#define L    8
#define RP1  10001
#define KPAD 10240            // padded K for probsf@emb_w (mult of 32)
#define NPADW 10112           // fc2_w rows padded to 79*128
#define SPLITK 10
#define KSPL 1024             // KPAD / SPLITK

// ---------------- scratch ----------------
__device__ float g_xT[Bb*L*E];                    // [t*1024+b][E] fp32 (concat0 source)
__device__ __nv_bfloat16 g_xhi[Bb*L*E];
__device__ __nv_bfloat16 g_xlo[Bb*L*E];
__device__ float g_hid[Bb*L*E];                   // [b][t][E]
__device__ float g_c[Bb*E];
__device__ __nv_bfloat16 g_hhi[Bb*E];
__device__ __nv_bfloat16 g_hlo[Bb*E];
__device__ float g_gates[Bb*4*E];
__device__ float g_gx[(size_t)Bb*L*4*E];          // [t*1024+b][4E]
__device__ __nv_bfloat16 g_cathi[Bb*2*E];
__device__ __nv_bfloat16 g_catlo[Bb*2*E];
__device__ __nv_bfloat16 g_h1hi[Bb*E];
__device__ __nv_bfloat16 g_h1lo[Bb*E];
__device__ __nv_bfloat16 g_psfhi[(size_t)Bb*KPAD];
__device__ __nv_bfloat16 g_psflo[(size_t)Bb*KPAD];
__device__ float g_psflast[Bb];
__device__ __nv_bfloat16 g_embThi[(size_t)E*KPAD]; // [e][k] K-major
__device__ __nv_bfloat16 g_embTlo[(size_t)E*KPAD];
__device__ __nv_bfloat16 g_fc2whi[(size_t)NPADW*E];
__device__ __nv_bfloat16 g_fc2wlo[(size_t)NPADW*E];
__device__ __nv_bfloat16 g_wihhi[4*E*E];
__device__ __nv_bfloat16 g_wihlo[4*E*E];
__device__ __nv_bfloat16 g_whhhi[4*E*E];
__device__ __nv_bfloat16 g_whhlo[4*E*E];
__device__ __nv_bfloat16 g_fc1whi[E*2*E];
__device__ __nv_bfloat16 g_fc1wlo[E*2*E];
__device__ float g_biassum[4*E];
__device__ float g_part[SPLITK*Bb*E];

// ---------------- ptx helpers ----------------
__device__ __forceinline__ uint32_t s2u(const void* p) {
    uint32_t a;
    asm("{ .reg .u64 t; cvta.to.shared.u64 t, %1; cvt.u32.u64 %0, t; }" : "=r"(a) : "l"(p));
    return a;
}
__device__ __forceinline__ void ldm4(uint32_t* r, uint32_t addr) {
    asm volatile("ldmatrix.sync.aligned.m8n8.x4.shared.b16 {%0,%1,%2,%3}, [%4];"
                 : "=r"(r[0]), "=r"(r[1]), "=r"(r[2]), "=r"(r[3]) : "r"(addr));
}
__device__ __forceinline__ void mma_bf16(float* d, const uint32_t* a, const uint32_t* b) {
    asm volatile("mma.sync.aligned.m16n8k16.row.col.f32.bf16.bf16.f32 "
                 "{%0,%1,%2,%3}, {%4,%5,%6,%7}, {%8,%9}, {%0,%1,%2,%3};"
                 : "+f"(d[0]), "+f"(d[1]), "+f"(d[2]), "+f"(d[3])
                 : "r"(a[0]), "r"(a[1]), "r"(a[2]), "r"(a[3]), "r"(b[0]), "r"(b[1]));
}
__device__ __forceinline__ void split_bf16(float x, __nv_bfloat16& h, __nv_bfloat16& l) {
    h = __float2bfloat16(x);
    l = __float2bfloat16(x - __bfloat162float(h));
}

// ---------------- warp-MMA split-bf16 GEMM ----------------
// C(128x128 tile) = (Ahi+Alo) @ (Bhi+Blo)^T via 3 passes, fp32 accum.
// A: [M][K] K-major bf16, B: [N][K] K-major bf16. Klen % 32 == 0.
// blockIdx.z: kbase = z*Klen, C += z*zstride (split-K partials).
// Epilogue: +bias[n], +Cin[m*ldc+n], RELU, and either fp32 C or split-bf16 (Ohi/Olo).
#define SSTR 40
template<bool RELU>
__global__ void __launch_bounds__(256)
hmma_gemm(const __nv_bfloat16* __restrict__ Ahi, const __nv_bfloat16* __restrict__ Alo, int lda,
          const __nv_bfloat16* __restrict__ Bhi, const __nv_bfloat16* __restrict__ Blo, int ldb,
          float* __restrict__ C, int ldc, int Nreal, int Klen, size_t zstride,
          const float* __restrict__ bias, const float* __restrict__ Cin,
          __nv_bfloat16* __restrict__ Ohi, __nv_bfloat16* __restrict__ Olo)
{
    __shared__ __nv_bfloat16 sAhi[128*SSTR], sAlo[128*SSTR];
    __shared__ __nv_bfloat16 sBhi[128*SSTR], sBlo[128*SSTR];

    const int tid = threadIdx.x, lane = tid & 31, wid = tid >> 5;
    const int bm = blockIdx.y * 128, bn = blockIdx.x * 128;
    const int kbase = blockIdx.z * Klen;
    C += (size_t)blockIdx.z * zstride;
    const int wm = (wid & 1) * 64, wn = (wid >> 1) * 32;

    float acc[4][4][4];
#pragma unroll
    for (int i = 0; i < 4; i++)
#pragma unroll
        for (int j = 0; j < 4; j++)
#pragma unroll
            for (int u = 0; u < 4; u++) acc[i][j][u] = 0.f;

    const uint32_t aHi = s2u(sAhi), aLo = s2u(sAlo);
    const uint32_t bHi = s2u(sBhi), bLo = s2u(sBlo);
    const int l15 = lane & 15, lq = lane >> 4;
    const int l8 = lane & 7, sel = lane >> 3;

    for (int kt = 0; kt < Klen; kt += 32) {
#pragma unroll
        for (int i = 0; i < 2; i++) {
            int idx = tid + i * 256;
            int row = idx >> 2, q = idx & 3;
            size_t ga = (size_t)(bm + row) * lda + kbase + kt + q * 8;
            size_t gb = (size_t)(bn + row) * ldb + kbase + kt + q * 8;
            int so = row * SSTR + q * 8;
            *(uint4*)&sAhi[so] = *(const uint4*)(Ahi + ga);
            *(uint4*)&sAlo[so] = *(const uint4*)(Alo + ga);
            *(uint4*)&sBhi[so] = *(const uint4*)(Bhi + gb);
            *(uint4*)&sBlo[so] = *(const uint4*)(Blo + gb);
        }
        __syncthreads();

#pragma unroll
        for (int ks = 0; ks < 2; ks++) {
            uint32_t ahi[4][4], alo[4][4];
#pragma unroll
            for (int mf = 0; mf < 4; mf++) {
                uint32_t off = (uint32_t)((wm + mf * 16 + l15) * SSTR + ks * 16 + lq * 8) * 2;
                ldm4(ahi[mf], aHi + off);
                ldm4(alo[mf], aLo + off);
            }
            uint32_t bhi[4][2], blo[4][2];
#pragma unroll
            for (int p = 0; p < 2; p++) {
                uint32_t off = (uint32_t)((wn + p * 16 + (sel >> 1) * 8 + l8) * SSTR
                                          + ks * 16 + (sel & 1) * 8) * 2;
                uint32_t r[4];
                ldm4(r, bHi + off);
                bhi[p*2][0] = r[0]; bhi[p*2][1] = r[1];
                bhi[p*2+1][0] = r[2]; bhi[p*2+1][1] = r[3];
                ldm4(r, bLo + off);
                blo[p*2][0] = r[0]; blo[p*2][1] = r[1];
                blo[p*2+1][0] = r[2]; blo[p*2+1][1] = r[3];
            }
#pragma unroll
            for (int mf = 0; mf < 4; mf++)
#pragma unroll
                for (int nf = 0; nf < 4; nf++) {
                    mma_bf16(acc[mf][nf], ahi[mf], bhi[nf]);
                    mma_bf16(acc[mf][nf], ahi[mf], blo[nf]);
                    mma_bf16(acc[mf][nf], alo[mf], bhi[nf]);
                }
        }
        __syncthreads();
    }

    const int crow = lane >> 2, ccol = (lane & 3) * 2;
#pragma unroll
    for (int mf = 0; mf < 4; mf++) {
        int r0 = bm + wm + mf * 16 + crow;
#pragma unroll
        for (int nf = 0; nf < 4; nf++) {
            int c0 = bn + wn + nf * 8 + ccol;
#pragma unroll
            for (int half = 0; half < 2; half++) {
                int r = r0 + half * 8;
#pragma unroll
                for (int u = 0; u < 2; u++) {
                    int n = c0 + u;
                    if (n < Nreal) {
                        float v = acc[mf][nf][half * 2 + u];
                        if (bias) v += bias[n];
                        if (Cin) v += Cin[(size_t)r * ldc + n];
                        if (RELU) v = fmaxf(v, 0.f);
                        if (Ohi) {
                            __nv_bfloat16 vh, vl;
                            split_bf16(v, vh, vl);
                            Ohi[(size_t)r * ldc + n] = vh;
                            Olo[(size_t)r * ldc + n] = vl;
                        } else {
                            C[(size_t)r * ldc + n] = v;
                        }
                    }
                }
            }
        }
    }
}

// ---------------- prep / elementwise kernels ----------------
__global__ void prep_bias_kernel(const float* __restrict__ b_ih, const float* __restrict__ b_hh) {
    int idx = blockIdx.x * 256 + threadIdx.x;
    if (idx < 4 * E) g_biassum[idx] = b_ih[idx] + b_hh[idx];
}

__global__ void conv_fc2w_kernel(const float* __restrict__ fc2_w) {
    int idx = blockIdx.x * 256 + threadIdx.x;      // NPADW*E
    int r = idx >> 8, c = idx & 255;
    float v = (r < RP1) ? fc2_w[r * E + c] : 0.f;
    split_bf16(v, g_fc2whi[idx], g_fc2wlo[idx]);
}

// convert w_ih, w_hh (each 4E x E) and fc1_w (E x 2E); total 3*262144 = 786432 elems
__global__ void conv_weights_kernel(const float* __restrict__ w_ih,
                                    const float* __restrict__ w_hh,
                                    const float* __restrict__ fc1_w) {
    int idx = blockIdx.x * 256 + threadIdx.x;
    if (idx < 4*E*E) {
        split_bf16(w_ih[idx], g_wihhi[idx], g_wihlo[idx]);
        split_bf16(w_hh[idx], g_whhhi[idx], g_whhlo[idx]);
    } else {
        int j = idx - 4*E*E;
        if (j < E*2*E) split_bf16(fc1_w[j], g_fc1whi[j], g_fc1wlo[j]);
    }
}

// coalesced transpose: emb_w [Rr][E] -> embT hi/lo [E][KPAD]
__global__ void conv_embT_kernel(const float* __restrict__ emb_w) {
    __shared__ float tile[32][33];
    int k0 = blockIdx.x * 32, e0 = blockIdx.y * 32;
    int tx = threadIdx.x & 31, ty = threadIdx.x >> 5;    // 32 x 8
#pragma unroll
    for (int r = 0; r < 32; r += 8) {
        int k = k0 + ty + r;
        tile[ty + r][tx] = (k < Rr) ? emb_w[(size_t)k * E + e0 + tx] : 0.f;
    }
    __syncthreads();
#pragma unroll
    for (int r = 0; r < 32; r += 8) {
        int e = e0 + ty + r;
        float v = tile[tx][ty + r];
        split_bf16(v, g_embThi[(size_t)e * KPAD + k0 + tx],
                      g_embTlo[(size_t)e * KPAD + k0 + tx]);
    }
}

__global__ void embed_kernel(const int* __restrict__ bodys, const float* __restrict__ emb_w) {
    int idx = blockIdx.x * 256 + threadIdx.x;      // B*L*E
    int e = idx & 255, b = (idx >> 8) & 1023, t = idx >> 18;
    float v = emb_w[(size_t)bodys[b * L + t] * E + e];
    g_xT[idx] = v;
    split_bf16(v, g_xhi[idx], g_xlo[idx]);
    if (idx < Bb * E) {
        g_c[idx] = 0.f;
        g_hhi[idx] = __float2bfloat16(0.f);
        g_hlo[idx] = __float2bfloat16(0.f);
    }
}

__device__ __forceinline__ float sigm(float x) { return 1.f / (1.f + __expf(-x)); }

__global__ void lstm_cell_kernel(int t) {
    int idx = blockIdx.x * 256 + threadIdx.x;      // B*E
    int b = idx >> 8, e = idx & 255;
    const float* g = g_gates + b * (4 * E);
    float gi = g[e], gf = g[E + e], gg = g[2 * E + e], go = g[3 * E + e];
    float cc = sigm(gf) * g_c[idx] + sigm(gi) * tanhf(gg);
    float hh = sigm(go) * tanhf(cc);
    g_c[idx] = cc;
    split_bf16(hh, g_hhi[idx], g_hlo[idx]);
    g_hid[b * (L * E) + t * E + e] = hh;
}

__global__ void concat0_kernel(float* __restrict__ out_emb) {
    int idx = blockIdx.x * 256 + threadIdx.x;      // B*512
    int b = idx >> 9, j = idx & 511;
    float v = (j < E) ? g_xT[b * E + j] : g_xT[(1024 + b) * E + (j - E)];
    out_emb[idx] = v;
    split_bf16(v, g_cathi[idx], g_catlo[idx]);
}

__global__ void emb1_finish_kernel(float* __restrict__ out_emb,
                                   const float* __restrict__ emb_w, int i) {
    int idx = blockIdx.x * 256 + threadIdx.x;      // B*E
    int b = idx >> 8, e = idx & 255;
    float s = 0.f;
#pragma unroll
    for (int p = 0; p < SPLITK; p++) s += g_part[p * (Bb * E) + idx];
    s += g_psflast[b] * g_hid[b * (L * E) + i * E + e];
    float sec = emb_w[(i + 1) * E + e];
    int o1 = b * (2 * E) + e, o2 = o1 + E;
    out_emb[o1] = s;
    out_emb[o2] = sec;
    split_bf16(s,   g_cathi[o1], g_catlo[o1]);
    split_bf16(sec, g_cathi[o2], g_catlo[o2]);
}

__global__ void softmax_kernel(const float* __restrict__ prob) {
    int b = blockIdx.x;
    const float* row = prob + (size_t)b * RP1;
    __nv_bfloat16* ohi = g_psfhi + (size_t)b * KPAD;
    __nv_bfloat16* olo = g_psflo + (size_t)b * KPAD;
    __shared__ float red[256];
    int t = threadIdx.x;
    float m = -1e30f;
    for (int j = t; j < RP1; j += 256) m = fmaxf(m, row[j]);
    red[t] = m; __syncthreads();
    for (int s = 128; s > 0; s >>= 1) { if (t < s) red[t] = fmaxf(red[t], red[t + s]); __syncthreads(); }
    m = red[0]; __syncthreads();
    float sum = 0.f;
    for (int j = t; j < RP1; j += 256) sum += __expf(row[j] - m);
    red[t] = sum; __syncthreads();
    for (int s = 128; s > 0; s >>= 1) { if (t < s) red[t] += red[t + s]; __syncthreads(); }
    float inv = 1.f / red[0];
    for (int j = t; j < KPAD; j += 256) {
        if (j < Rr) {
            float v = __expf(row[j] - m) * inv;
            split_bf16(v, ohi[j], olo[j]);
        } else {
            if (j == Rr) g_psflast[b] = __expf(row[j] - m) * inv;
            ohi[j] = __float2bfloat16(0.f);
            olo[j] = __float2bfloat16(0.f);
        }
    }
}

// ---------------- launch ----------------
extern "C" void kernel_launch(void* const* d_in, const int* in_sizes, int n_in,
                              void* d_out, int out_size) {
    const int*   bodys = (const int*)  d_in[0];
    const float* emb_w = (const float*)d_in[1];
    const float* w_ih  = (const float*)d_in[2];
    const float* w_hh  = (const float*)d_in[3];
    const float* b_ih  = (const float*)d_in[4];
    const float* b_hh  = (const float*)d_in[5];
    const float* fc1_w = (const float*)d_in[6];
    const float* fc1_b = (const float*)d_in[7];
    const float* fc2_w = (const float*)d_in[8];
    const float* fc2_b = (const float*)d_in[9];

    float* out_prob = (float*)d_out;
    float* out_emb  = out_prob + (size_t)Bb * RP1;

    float *biassum, *part, *gx, *gates;
    __nv_bfloat16 *xhi, *xlo, *hhi, *hlo, *cathi, *catlo, *h1hi, *h1lo;
    __nv_bfloat16 *psfhi, *psflo, *eThi, *eTlo, *f2hi, *f2lo;
    __nv_bfloat16 *wihhi, *wihlo, *whhhi, *whhlo, *f1hi, *f1lo;
    cudaGetSymbolAddress((void**)&biassum, g_biassum);
    cudaGetSymbolAddress((void**)&part,    g_part);
    cudaGetSymbolAddress((void**)&gx,      g_gx);
    cudaGetSymbolAddress((void**)&gates,   g_gates);
    cudaGetSymbolAddress((void**)&xhi,     g_xhi);
    cudaGetSymbolAddress((void**)&xlo,     g_xlo);
    cudaGetSymbolAddress((void**)&hhi,     g_hhi);
    cudaGetSymbolAddress((void**)&hlo,     g_hlo);
    cudaGetSymbolAddress((void**)&cathi,   g_cathi);
    cudaGetSymbolAddress((void**)&catlo,   g_catlo);
    cudaGetSymbolAddress((void**)&h1hi,    g_h1hi);
    cudaGetSymbolAddress((void**)&h1lo,    g_h1lo);
    cudaGetSymbolAddress((void**)&psfhi,   g_psfhi);
    cudaGetSymbolAddress((void**)&psflo,   g_psflo);
    cudaGetSymbolAddress((void**)&eThi,    g_embThi);
    cudaGetSymbolAddress((void**)&eTlo,    g_embTlo);
    cudaGetSymbolAddress((void**)&f2hi,    g_fc2whi);
    cudaGetSymbolAddress((void**)&f2lo,    g_fc2wlo);
    cudaGetSymbolAddress((void**)&wihhi,   g_wihhi);
    cudaGetSymbolAddress((void**)&wihlo,   g_wihlo);
    cudaGetSymbolAddress((void**)&whhhi,   g_whhhi);
    cudaGetSymbolAddress((void**)&whhlo,   g_whhlo);
    cudaGetSymbolAddress((void**)&f1hi,    g_fc1whi);
    cudaGetSymbolAddress((void**)&f1lo,    g_fc1wlo);

    prep_bias_kernel<<<4, 256>>>(b_ih, b_hh);
    conv_fc2w_kernel<<<(NPADW * E) / 256, 256>>>(fc2_w);
    conv_weights_kernel<<<(4*E*E + E*2*E + 255) / 256 + 1, 256>>>(w_ih, w_hh, fc1_w);
    conv_embT_kernel<<<dim3(KPAD / 32, E / 32), 256>>>(emb_w);
    embed_kernel<<<8192, 256>>>(bodys, emb_w);

    // gx = x @ w_ih^T + biassum  : HMMA, M=8192, N=1024, K=256
    hmma_gemm<false><<<dim3(8, 64), 256>>>(
        xhi, xlo, E, wihhi, wihlo, E,
        gx, 4 * E, 4 * E, E, 0, biassum, nullptr, nullptr, nullptr);

    // LSTM steps: gates = h @ w_hh^T + gx_t : HMMA with addend
    for (int t = 0; t < L; t++) {
        hmma_gemm<false><<<dim3(8, 8), 256>>>(
            hhi, hlo, E, whhhi, whhlo, E,
            gates, 4 * E, 4 * E, E, 0,
            nullptr, gx + (size_t)t * Bb * 4 * E, nullptr, nullptr);
        lstm_cell_kernel<<<1024, 256>>>(t);
    }

    for (int i = 0; i < L - 1; i++) {
        if (i == 0) {
            concat0_kernel<<<2048, 256>>>(out_emb);
        } else {
            // emb_1 = prob_sf[:, :R] @ emb_w : HMMA split-K x10
            hmma_gemm<false><<<dim3(2, 8, SPLITK), 256>>>(
                psfhi, psflo, KPAD, eThi, eTlo, KPAD,
                part, E, E, KSPL, (size_t)Bb * E, nullptr, nullptr, nullptr, nullptr);
            emb1_finish_kernel<<<1024, 256>>>(out_emb, emb_w, i);
        }
        // hidden1 = relu(emb_concat @ fc1_w^T + fc1_b) -> split bf16 direct
        hmma_gemm<true><<<dim3(2, 8), 256>>>(
            cathi, catlo, 2 * E, f1hi, f1lo, 2 * E,
            nullptr, E, E, 2 * E, 0, fc1_b, nullptr, h1hi, h1lo);
        // prob = hidden1 @ fc2_w^T + fc2_b
        hmma_gemm<false><<<dim3(79, 8), 256>>>(
            h1hi, h1lo, E, f2hi, f2lo, E,
            out_prob, RP1, RP1, E, 0, fc2_b, nullptr, nullptr, nullptr);
        if (i < L - 2) softmax_kernel<<<1024, 256>>>(out_prob);
    }
}

// round 7
// speedup vs baseline: 1.1968x; 1.1968x over previous
#include <cuda_runtime.h>
#include <cuda_bf16.h>
#include <math.h>
#include <stdint.h>

#define Rr   10000
#define E    256
#define Bb   1024
#define L    8
#define RP1  10001
#define KPAD 10240            // padded K for probsf@emb_w (mult of 32)
#define NPADW 10112           // fc2_w rows padded to 79*128
#define SPLITK 10
#define KSPL 1024             // KPAD / SPLITK

// packed f32x2 helpers (Blackwell FFMA2)
#define PACKF2(d, lo, hi) asm("mov.b64 %0, {%1, %2};" : "=l"(d) : "f"(lo), "f"(hi))
#define FMAF2(acc, a, b)  asm("fma.rn.f32x2 %0, %1, %2, %0;" : "+l"(acc) : "l"(a), "l"(b))
#define UNPACKF2(lo, hi, v) asm("mov.b64 {%0, %1}, %2;" : "=f"(lo), "=f"(hi) : "l"(v))

// ---------------- scratch ----------------
__device__ float g_xT[Bb*L*E];                    // [t*1024+b][E] fp32
__device__ __nv_bfloat16 g_xhi[Bb*L*E];
__device__ __nv_bfloat16 g_xlo[Bb*L*E];
__device__ float g_hid[Bb*L*E];                   // [b][t][E]
__device__ float g_h[Bb*E];
__device__ float g_c[Bb*E];
__device__ float g_gates[Bb*4*E];
__device__ float g_gx[(size_t)Bb*L*4*E];          // [t*1024+b][4E]
__device__ float g_hidden1[Bb*E];
__device__ __nv_bfloat16 g_h1hi[Bb*E];
__device__ __nv_bfloat16 g_h1lo[Bb*E];
__device__ __nv_bfloat16 g_psfhi[(size_t)Bb*KPAD];
__device__ __nv_bfloat16 g_psflo[(size_t)Bb*KPAD];
__device__ float g_psflast[Bb];
__device__ __nv_bfloat16 g_embThi[(size_t)E*KPAD]; // [e][k] K-major
__device__ __nv_bfloat16 g_embTlo[(size_t)E*KPAD];
__device__ __nv_bfloat16 g_fc2whi[(size_t)NPADW*E];
__device__ __nv_bfloat16 g_fc2wlo[(size_t)NPADW*E];
__device__ __nv_bfloat16 g_wihhi[4*E*E];
__device__ __nv_bfloat16 g_wihlo[4*E*E];
__device__ float g_biassum[4*E];
__device__ float g_part[SPLITK*Bb*E];

// ---------------- ptx helpers ----------------
__device__ __forceinline__ uint32_t s2u(const void* p) {
    uint32_t a;
    asm("{ .reg .u64 t; cvta.to.shared.u64 t, %1; cvt.u32.u64 %0, t; }" : "=r"(a) : "l"(p));
    return a;
}
__device__ __forceinline__ void ldm4(uint32_t* r, uint32_t addr) {
    asm volatile("ldmatrix.sync.aligned.m8n8.x4.shared.b16 {%0,%1,%2,%3}, [%4];"
                 : "=r"(r[0]), "=r"(r[1]), "=r"(r[2]), "=r"(r[3]) : "r"(addr));
}
__device__ __forceinline__ void mma_bf16(float* d, const uint32_t* a, const uint32_t* b) {
    asm volatile("mma.sync.aligned.m16n8k16.row.col.f32.bf16.bf16.f32 "
                 "{%0,%1,%2,%3}, {%4,%5,%6,%7}, {%8,%9}, {%0,%1,%2,%3};"
                 : "+f"(d[0]), "+f"(d[1]), "+f"(d[2]), "+f"(d[3])
                 : "r"(a[0]), "r"(a[1]), "r"(a[2]), "r"(a[3]), "r"(b[0]), "r"(b[1]));
}
__device__ __forceinline__ void cpa16(uint32_t saddr, const void* gptr) {
    asm volatile("cp.async.cg.shared.global [%0], [%1], 16;" :: "r"(saddr), "l"(gptr) : "memory");
}
#define CP_COMMIT() asm volatile("cp.async.commit_group;" ::: "memory")
#define CP_WAIT1()  asm volatile("cp.async.wait_group 1;" ::: "memory")
#define CP_WAIT0()  asm volatile("cp.async.wait_group 0;" ::: "memory")

__device__ __forceinline__ void split_bf16(float x, __nv_bfloat16& h, __nv_bfloat16& l) {
    h = __float2bfloat16(x);
    l = __float2bfloat16(x - __bfloat162float(h));
}

// ---------------- double-buffered warp-MMA split-bf16 GEMM ----------------
// C(128x128 tile) = (Ahi+Alo) @ (Bhi+Blo)^T via 3 passes, fp32 accum.
// A: [M][K] K-major bf16, B: [N][K] K-major bf16. Klen % 32 == 0.
// blockIdx.z: kbase = z*Klen, C += z*zstride (split-K partials).
#define SSTR 40
#define STAGE_B 40960          // 4 arrays * 128*SSTR*2 bytes
#define HMMA_SMEM (2*STAGE_B)  // 81920 bytes dynamic
__global__ void __launch_bounds__(256)
hmma_gemm(const __nv_bfloat16* __restrict__ Ahi, const __nv_bfloat16* __restrict__ Alo, int lda,
          const __nv_bfloat16* __restrict__ Bhi, const __nv_bfloat16* __restrict__ Blo, int ldb,
          float* __restrict__ C, int ldc, int Nreal, int Klen, size_t zstride,
          const float* __restrict__ bias)
{
    extern __shared__ char dsm[];
    const uint32_t sb = s2u(dsm);

    const int tid = threadIdx.x, lane = tid & 31, wid = tid >> 5;
    const int bm = blockIdx.y * 128, bn = blockIdx.x * 128;
    const int kbase = blockIdx.z * Klen;
    C += (size_t)blockIdx.z * zstride;
    const int wm = (wid & 1) * 64, wn = (wid >> 1) * 32;

    float acc[4][4][4];
#pragma unroll
    for (int i = 0; i < 4; i++)
#pragma unroll
        for (int j = 0; j < 4; j++)
#pragma unroll
            for (int u = 0; u < 4; u++) acc[i][j][u] = 0.f;

    const int l15 = lane & 15, lq = lane >> 4;
    const int l8 = lane & 7, sel = lane >> 3;

    // per-thread load coords (2 chunks of 16B per array per stage)
    const int row0 = tid >> 2, q0 = tid & 3;           // rows 0..63
    const int row1 = row0 + 64, q1 = q0;               // rows 64..127

    const int ntiles = Klen >> 5;

    // prologue: issue stage 0 (kt = 0)
    {
        size_t ga0 = (size_t)(bm + row0) * lda + kbase + q0 * 8;
        size_t gb0 = (size_t)(bn + row0) * ldb + kbase + q0 * 8;
        size_t ga1 = (size_t)(bm + row1) * lda + kbase + q1 * 8;
        size_t gb1 = (size_t)(bn + row1) * ldb + kbase + q1 * 8;
        uint32_t s0 = sb + (uint32_t)(row0 * SSTR + q0 * 8) * 2;
        uint32_t s1 = sb + (uint32_t)(row1 * SSTR + q1 * 8) * 2;
        cpa16(s0,         Ahi + ga0); cpa16(s0 + 10240, Alo + ga0);
        cpa16(s0 + 20480, Bhi + gb0); cpa16(s0 + 30720, Blo + gb0);
        cpa16(s1,         Ahi + ga1); cpa16(s1 + 10240, Alo + ga1);
        cpa16(s1 + 20480, Bhi + gb1); cpa16(s1 + 30720, Blo + gb1);
        CP_COMMIT();
    }

    for (int t = 0; t < ntiles; t++) {
        if (t + 1 < ntiles) {
            int kt = kbase + (t + 1) * 32;
            uint32_t stb = sb + ((t + 1) & 1) * STAGE_B;
            size_t ga0 = (size_t)(bm + row0) * lda + kt + q0 * 8;
            size_t gb0 = (size_t)(bn + row0) * ldb + kt + q0 * 8;
            size_t ga1 = (size_t)(bm + row1) * lda + kt + q1 * 8;
            size_t gb1 = (size_t)(bn + row1) * ldb + kt + q1 * 8;
            uint32_t s0 = stb + (uint32_t)(row0 * SSTR + q0 * 8) * 2;
            uint32_t s1 = stb + (uint32_t)(row1 * SSTR + q1 * 8) * 2;
            cpa16(s0,         Ahi + ga0); cpa16(s0 + 10240, Alo + ga0);
            cpa16(s0 + 20480, Bhi + gb0); cpa16(s0 + 30720, Blo + gb0);
            cpa16(s1,         Ahi + ga1); cpa16(s1 + 10240, Alo + ga1);
            cpa16(s1 + 20480, Bhi + gb1); cpa16(s1 + 30720, Blo + gb1);
            CP_COMMIT();
            CP_WAIT1();
        } else {
            CP_WAIT0();
        }
        __syncthreads();

        const uint32_t stb = sb + (t & 1) * STAGE_B;
        const uint32_t aHi = stb, aLo = stb + 10240, bHi = stb + 20480, bLo = stb + 30720;

#pragma unroll
        for (int ks = 0; ks < 2; ks++) {
            uint32_t ahi[4][4], alo[4][4];
#pragma unroll
            for (int mf = 0; mf < 4; mf++) {
                uint32_t off = (uint32_t)((wm + mf * 16 + l15) * SSTR + ks * 16 + lq * 8) * 2;
                ldm4(ahi[mf], aHi + off);
                ldm4(alo[mf], aLo + off);
            }
            uint32_t bhi[4][2], blo[4][2];
#pragma unroll
            for (int p = 0; p < 2; p++) {
                uint32_t off = (uint32_t)((wn + p * 16 + (sel >> 1) * 8 + l8) * SSTR
                                          + ks * 16 + (sel & 1) * 8) * 2;
                uint32_t r[4];
                ldm4(r, bHi + off);
                bhi[p*2][0] = r[0]; bhi[p*2][1] = r[1];
                bhi[p*2+1][0] = r[2]; bhi[p*2+1][1] = r[3];
                ldm4(r, bLo + off);
                blo[p*2][0] = r[0]; blo[p*2][1] = r[1];
                blo[p*2+1][0] = r[2]; blo[p*2+1][1] = r[3];
            }
#pragma unroll
            for (int mf = 0; mf < 4; mf++)
#pragma unroll
                for (int nf = 0; nf < 4; nf++) {
                    mma_bf16(acc[mf][nf], ahi[mf], bhi[nf]);
                    mma_bf16(acc[mf][nf], ahi[mf], blo[nf]);
                    mma_bf16(acc[mf][nf], alo[mf], bhi[nf]);
                }
        }
        __syncthreads();
    }

    const int crow = lane >> 2, ccol = (lane & 3) * 2;
#pragma unroll
    for (int mf = 0; mf < 4; mf++) {
        int r0 = bm + wm + mf * 16 + crow;
#pragma unroll
        for (int nf = 0; nf < 4; nf++) {
            int c0 = bn + wn + nf * 8 + ccol;
#pragma unroll
            for (int half = 0; half < 2; half++) {
                int r = r0 + half * 8;
#pragma unroll
                for (int u = 0; u < 2; u++) {
                    int n = c0 + u;
                    if (n < Nreal) {
                        float v = acc[mf][nf][half * 2 + u];
                        if (bias) v += bias[n];
                        C[(size_t)r * ldc + n] = v;
                    }
                }
            }
        }
    }
}

// ---------------- prep / elementwise kernels ----------------
__global__ void prep_bias_kernel(const float* __restrict__ b_ih, const float* __restrict__ b_hh) {
    int idx = blockIdx.x * 256 + threadIdx.x;
    if (idx < 4 * E) g_biassum[idx] = b_ih[idx] + b_hh[idx];
}

__global__ void conv_fc2w_kernel(const float* __restrict__ fc2_w) {
    int idx = blockIdx.x * 256 + threadIdx.x;      // NPADW*E
    int r = idx >> 8, c = idx & 255;
    float v = (r < RP1) ? fc2_w[r * E + c] : 0.f;
    split_bf16(v, g_fc2whi[idx], g_fc2wlo[idx]);
}

__global__ void conv_wih_kernel(const float* __restrict__ w_ih) {
    int idx = blockIdx.x * 256 + threadIdx.x;      // 4E*E
    split_bf16(w_ih[idx], g_wihhi[idx], g_wihlo[idx]);
}

// coalesced transpose: emb_w [Rr][E] -> embT hi/lo [E][KPAD]
__global__ void conv_embT_kernel(const float* __restrict__ emb_w) {
    __shared__ float tile[32][33];
    int k0 = blockIdx.x * 32, e0 = blockIdx.y * 32;
    int tx = threadIdx.x & 31, ty = threadIdx.x >> 5;    // 32 x 8
#pragma unroll
    for (int r = 0; r < 32; r += 8) {
        int k = k0 + ty + r;
        tile[ty + r][tx] = (k < Rr) ? emb_w[(size_t)k * E + e0 + tx] : 0.f;
    }
    __syncthreads();
#pragma unroll
    for (int r = 0; r < 32; r += 8) {
        int e = e0 + ty + r;
        float v = tile[tx][ty + r];
        split_bf16(v, g_embThi[(size_t)e * KPAD + k0 + tx],
                      g_embTlo[(size_t)e * KPAD + k0 + tx]);
    }
}

__global__ void embed_kernel(const int* __restrict__ bodys, const float* __restrict__ emb_w) {
    int idx = blockIdx.x * 256 + threadIdx.x;      // B*L*E
    int e = idx & 255, b = (idx >> 8) & 1023, t = idx >> 18;
    float v = emb_w[(size_t)bodys[b * L + t] * E + e];
    g_xT[idx] = v;
    split_bf16(v, g_xhi[idx], g_xlo[idx]);
    if (idx < Bb * E) { g_h[idx] = 0.f; g_c[idx] = 0.f; }
}

__device__ __forceinline__ float sigm(float x) { return 1.f / (1.f + __expf(-x)); }

__global__ void lstm_cell_kernel(int t) {
    int idx = blockIdx.x * 256 + threadIdx.x;      // B*E
    int b = idx >> 8, e = idx & 255;
    const float* g = g_gates + b * (4 * E);
    float gi = g[e], gf = g[E + e], gg = g[2 * E + e], go = g[3 * E + e];
    float cc = sigm(gf) * g_c[idx] + sigm(gi) * tanhf(gg);
    float hh = sigm(go) * tanhf(cc);
    g_c[idx] = cc; g_h[idx] = hh;
    g_hid[b * (L * E) + t * E + e] = hh;
}

__global__ void concat0_kernel(float* __restrict__ out_emb) {
    int idx = blockIdx.x * 256 + threadIdx.x;      // B*512
    int b = idx >> 9, j = idx & 511;
    out_emb[idx] = (j < E) ? g_xT[b * E + j] : g_xT[(1024 + b) * E + (j - E)];
}

__global__ void emb1_finish_kernel(float* __restrict__ out_emb,
                                   const float* __restrict__ emb_w, int i) {
    int idx = blockIdx.x * 256 + threadIdx.x;      // B*E
    int b = idx >> 8, e = idx & 255;
    float s = 0.f;
#pragma unroll
    for (int p = 0; p < SPLITK; p++) s += g_part[p * (Bb * E) + idx];
    s += g_psflast[b] * g_hid[b * (L * E) + i * E + e];
    out_emb[b * (2 * E) + e]     = s;
    out_emb[b * (2 * E) + E + e] = emb_w[(i + 1) * E + e];
}

__global__ void conv_h1_kernel() {
    int idx = blockIdx.x * 256 + threadIdx.x;      // B*E
    split_bf16(g_hidden1[idx], g_h1hi[idx], g_h1lo[idx]);
}

__global__ void softmax_kernel(const float* __restrict__ prob) {
    int b = blockIdx.x;
    const float* row = prob + (size_t)b * RP1;
    __nv_bfloat16* ohi = g_psfhi + (size_t)b * KPAD;
    __nv_bfloat16* olo = g_psflo + (size_t)b * KPAD;
    __shared__ float red[256];
    int t = threadIdx.x;
    float m = -1e30f;
    for (int j = t; j < RP1; j += 256) m = fmaxf(m, row[j]);
    red[t] = m; __syncthreads();
    for (int s = 128; s > 0; s >>= 1) { if (t < s) red[t] = fmaxf(red[t], red[t + s]); __syncthreads(); }
    m = red[0]; __syncthreads();
    float sum = 0.f;
    for (int j = t; j < RP1; j += 256) sum += __expf(row[j] - m);
    red[t] = sum; __syncthreads();
    for (int s = 128; s > 0; s >>= 1) { if (t < s) red[t] += red[t + s]; __syncthreads(); }
    float inv = 1.f / red[0];
    for (int j = t; j < KPAD; j += 256) {
        if (j < Rr) {
            float v = __expf(row[j] - m) * inv;
            split_bf16(v, ohi[j], olo[j]);
        } else {
            if (j == Rr) g_psflast[b] = __expf(row[j] - m) * inv;
            ohi[j] = __float2bfloat16(0.f);
            olo[j] = __float2bfloat16(0.f);
        }
    }
}

// ---------------- 64x64 FFMA2 GEMM with optional addend (LSTM step, fc1) ----------------
#define BMT 64
#define BNT 64
#define BKT 16
template<bool TRANSB, bool RELU>
__global__ void gemm_kernel(const float* __restrict__ A, int lda,
                            const float* __restrict__ B, int ldb,
                            float* __restrict__ C, int ldc,
                            int M, int N, int Klen,
                            const float* __restrict__ bias,
                            const float* __restrict__ Cin, int ldcin)
{
    __shared__ float As[BKT][BMT + 4];
    __shared__ float Bs[BKT][BNT + 4];
    int bm = blockIdx.y * BMT, bn = blockIdx.x * BNT;
    int tid = threadIdx.x;
    int tx = tid & 15, ty = tid >> 4;
    unsigned long long acc[4][2];
#pragma unroll
    for (int i = 0; i < 4; i++) { acc[i][0] = 0ULL; acc[i][1] = 0ULL; }

    for (int kt = 0; kt < Klen; kt += BKT) {
#pragma unroll
        for (int j = 0; j < 4; j++) {
            int idx = tid + j * 256;
            int m = idx >> 4, k = idx & 15;
            As[k][m] = A[(size_t)(bm + m) * lda + kt + k];
        }
#pragma unroll
        for (int j = 0; j < 4; j++) {
            int idx = tid + j * 256;
            if (TRANSB) {
                int n = idx >> 4, k = idx & 15;
                Bs[k][n] = (bn + n < N) ? B[(size_t)(bn + n) * ldb + kt + k] : 0.f;
            } else {
                int k = idx >> 6, n = idx & 63;
                Bs[k][n] = (bn + n < N) ? B[(size_t)(kt + k) * ldb + bn + n] : 0.f;
            }
        }
        __syncthreads();
#pragma unroll
        for (int kk = 0; kk < BKT; kk++) {
            float4 a4 = *(const float4*)&As[kk][ty * 4];
            float4 b4 = *(const float4*)&Bs[kk][tx * 4];
            unsigned long long bp0, bp1;
            PACKF2(bp0, b4.x, b4.y); PACKF2(bp1, b4.z, b4.w);
            float av[4] = {a4.x, a4.y, a4.z, a4.w};
#pragma unroll
            for (int i = 0; i < 4; i++) {
                unsigned long long a2;
                PACKF2(a2, av[i], av[i]);
                FMAF2(acc[i][0], a2, bp0);
                FMAF2(acc[i][1], a2, bp1);
            }
        }
        __syncthreads();
    }
#pragma unroll
    for (int i = 0; i < 4; i++) {
        int m = bm + ty * 4 + i;
#pragma unroll
        for (int j = 0; j < 2; j++) {
            int nbase = bn + tx * 4 + 2 * j;
            float lo, hi;
            UNPACKF2(lo, hi, acc[i][j]);
#pragma unroll
            for (int u = 0; u < 2; u++) {
                int n = nbase + u;
                if (n < N) {
                    float v = (u == 0) ? lo : hi;
                    if (Cin) v += Cin[(size_t)m * ldcin + n];
                    else if (bias) v += bias[n];
                    if (RELU) v = fmaxf(v, 0.f);
                    C[(size_t)m * ldc + n] = v;
                }
            }
        }
    }
}

// ---------------- launch ----------------
extern "C" void kernel_launch(void* const* d_in, const int* in_sizes, int n_in,
                              void* d_out, int out_size) {
    const int*   bodys = (const int*)  d_in[0];
    const float* emb_w = (const float*)d_in[1];
    const float* w_ih  = (const float*)d_in[2];
    const float* w_hh  = (const float*)d_in[3];
    const float* b_ih  = (const float*)d_in[4];
    const float* b_hh  = (const float*)d_in[5];
    const float* fc1_w = (const float*)d_in[6];
    const float* fc1_b = (const float*)d_in[7];
    const float* fc2_w = (const float*)d_in[8];
    const float* fc2_b = (const float*)d_in[9];

    float* out_prob = (float*)d_out;
    float* out_emb  = out_prob + (size_t)Bb * RP1;

    cudaFuncSetAttribute(hmma_gemm, cudaFuncAttributeMaxDynamicSharedMemorySize, HMMA_SMEM);

    float *hidden1, *biassum, *part, *gx, *h, *gates;
    __nv_bfloat16 *xhi, *xlo, *h1hi, *h1lo, *psfhi, *psflo, *eThi, *eTlo, *f2hi, *f2lo, *wihhi, *wihlo;
    cudaGetSymbolAddress((void**)&hidden1, g_hidden1);
    cudaGetSymbolAddress((void**)&biassum, g_biassum);
    cudaGetSymbolAddress((void**)&part,    g_part);
    cudaGetSymbolAddress((void**)&gx,      g_gx);
    cudaGetSymbolAddress((void**)&h,       g_h);
    cudaGetSymbolAddress((void**)&gates,   g_gates);
    cudaGetSymbolAddress((void**)&xhi,     g_xhi);
    cudaGetSymbolAddress((void**)&xlo,     g_xlo);
    cudaGetSymbolAddress((void**)&h1hi,    g_h1hi);
    cudaGetSymbolAddress((void**)&h1lo,    g_h1lo);
    cudaGetSymbolAddress((void**)&psfhi,   g_psfhi);
    cudaGetSymbolAddress((void**)&psflo,   g_psflo);
    cudaGetSymbolAddress((void**)&eThi,    g_embThi);
    cudaGetSymbolAddress((void**)&eTlo,    g_embTlo);
    cudaGetSymbolAddress((void**)&f2hi,    g_fc2whi);
    cudaGetSymbolAddress((void**)&f2lo,    g_fc2wlo);
    cudaGetSymbolAddress((void**)&wihhi,   g_wihhi);
    cudaGetSymbolAddress((void**)&wihlo,   g_wihlo);

    prep_bias_kernel<<<4, 256>>>(b_ih, b_hh);
    conv_fc2w_kernel<<<(NPADW * E) / 256, 256>>>(fc2_w);
    conv_wih_kernel<<<(4 * E * E) / 256, 256>>>(w_ih);
    conv_embT_kernel<<<dim3(KPAD / 32, E / 32), 256>>>(emb_w);
    embed_kernel<<<8192, 256>>>(bodys, emb_w);

    // gx = x @ w_ih^T + biassum : HMMA, grid 8x64 = 512 CTAs
    hmma_gemm<<<dim3(8, 64), 256, HMMA_SMEM>>>(
        xhi, xlo, E, wihhi, wihlo, E,
        gx, 4 * E, 4 * E, E, 0, biassum);

    // LSTM steps: gates = h @ w_hh^T + gx_t : FFMA2 full-chip
    for (int t = 0; t < L; t++) {
        gemm_kernel<true, false><<<dim3(16, 16), 256>>>(
            h, E, w_hh, E, gates, 4 * E, Bb, 4 * E, E,
            nullptr, gx + (size_t)t * Bb * 4 * E, 4 * E);
        lstm_cell_kernel<<<1024, 256>>>(t);
    }

    for (int i = 0; i < L - 1; i++) {
        if (i == 0) {
            concat0_kernel<<<2048, 256>>>(out_emb);
        } else {
            // emb_1 = prob_sf[:, :R] @ emb_w : HMMA split-K x10
            hmma_gemm<<<dim3(2, 8, SPLITK), 256, HMMA_SMEM>>>(
                psfhi, psflo, KPAD, eThi, eTlo, KPAD,
                part, E, E, KSPL, (size_t)Bb * E, nullptr);
            emb1_finish_kernel<<<1024, 256>>>(out_emb, emb_w, i);
        }
        // hidden1 = relu(emb_concat @ fc1_w^T + fc1_b) : FFMA2
        gemm_kernel<true, true><<<dim3(4, 16), 256>>>(
            out_emb, 2 * E, fc1_w, 2 * E, hidden1, E, Bb, E, 2 * E,
            fc1_b, nullptr, 0);
        conv_h1_kernel<<<1024, 256>>>();
        // prob = hidden1 @ fc2_w^T + fc2_b : HMMA
        hmma_gemm<<<dim3(79, 8), 256, HMMA_SMEM>>>(
            h1hi, h1lo, E, f2hi, f2lo, E,
            out_prob, RP1, RP1, E, 0, fc2_b);
        if (i < L - 2) softmax_kernel<<<1024, 256>>>(out_prob);
    }
}